// round 11
// baseline (speedup 1.0000x reference)
#include <cuda_runtime.h>
#include <cuda_fp16.h>
#include <cstdint>

#define MAXN 100000
#define MAXE 600000
#define F1 128
#define F2 64
#define SCAN_T 256

// Scratch: __device__ globals (allocation-free rule), referenced directly as symbols.
__device__ __half g_h1h[MAXN * F1];   // x @ W1 (fp16, gather operand)
__device__ float  g_agg1[MAXN * F1];  // aggregated layer-1 (fp32, pre-bias/relu)
__device__ __half g_h2h[MAXN * F2];   // relu(agg1+b1) @ W2 (fp16, gather operand)
__device__ float  g_dinv[MAXN];       // rsqrt(deg+1)
__device__ int    g_eidx[2 * MAXE];   // normalized int32 edge index [src | dst]
__device__ int    g_is32 = 0;         // != 0 if raw edge buffer is int32 (idempotent across calls)
__device__ int    g_deg[MAXN];        // in-degree (excl self-loop)
__device__ int    g_rowptr[MAXN + 1]; // CSR row pointers (by dst)
__device__ int    g_cnt[MAXN];        // fill counters
__device__ int    g_col[MAXE];        // CSR: src per edge
__device__ float  g_wsrc[MAXE];       // CSR: dinv[src] per edge
__device__ int    g_bsum[1024];       // block sums for scan

// ---------------- tf32 helpers ----------------
__device__ __forceinline__ uint32_t f2tf(float f) {
    uint32_t u;
    asm("cvt.rna.tf32.f32 %0, %1;" : "=r"(u) : "f"(f));
    return u;
}
__device__ __forceinline__ void mma_tf32(float* c, uint32_t a0, uint32_t a1, uint32_t a2,
                                         uint32_t a3, uint32_t b0, uint32_t b1) {
    asm volatile(
        "mma.sync.aligned.m16n8k8.row.col.f32.tf32.tf32.f32 "
        "{%0,%1,%2,%3}, {%4,%5,%6,%7}, {%8,%9}, {%0,%1,%2,%3};"
        : "+f"(c[0]), "+f"(c[1]), "+f"(c[2]), "+f"(c[3])
        : "r"(a0), "r"(a1), "r"(a2), "r"(a3), "r"(b0), "r"(b1));
}

// ---------------- edge dtype detection (+ zero degree histogram) ----------------
__global__ void detect_kernel(const void* __restrict__ ei_raw, int E, int n) {
    const long long* p = (const long long*)ei_raw;
    int lbad = 0;
    for (int i = blockIdx.x * blockDim.x + threadIdx.x; i < E; i += gridDim.x * blockDim.x) {
        long long v = p[i];
        if (v < 0 || v >= (long long)n) lbad = 1;
    }
    for (int i = blockIdx.x * blockDim.x + threadIdx.x; i < n; i += gridDim.x * blockDim.x)
        g_deg[i] = 0;
    if (__syncthreads_or(lbad) && threadIdx.x == 0) atomicOr(&g_is32, 1);
}

// normalize edges to int32 + count in-degrees (dst half) in one pass
__global__ void convert_kernel(const void* __restrict__ ei_raw, int E, int n) {
    int i = blockIdx.x * blockDim.x + threadIdx.x;
    if (i >= 2 * E) return;
    int v;
    if (g_is32) v = ((const int*)ei_raw)[i];
    else        v = (int)((const long long*)ei_raw)[i];
    v = v < 0 ? 0 : (v >= n ? n - 1 : v);
    g_eidx[i] = v;
    if (i >= E) atomicAdd(&g_deg[v], 1);  // dst half
}

// ---------------- CSR build ----------------
__global__ void scan1_kernel(int n) {
    __shared__ int sh[SCAN_T];
    int i = blockIdx.x * SCAN_T + threadIdx.x;
    int v = (i < n) ? g_deg[i] : 0;
    sh[threadIdx.x] = v;
    __syncthreads();
    int acc = v;
#pragma unroll
    for (int off = 1; off < SCAN_T; off <<= 1) {
        int t = (threadIdx.x >= off) ? sh[threadIdx.x - off] : 0;
        __syncthreads();
        acc += t;
        sh[threadIdx.x] = acc;
        __syncthreads();
    }
    if (i < n) g_rowptr[i] = acc - v;  // exclusive
    if (threadIdx.x == SCAN_T - 1) g_bsum[blockIdx.x] = acc;
}

__global__ void scan2_kernel(int nb) {
    __shared__ int sh[1024];
    int v = (threadIdx.x < nb) ? g_bsum[threadIdx.x] : 0;
    sh[threadIdx.x] = v;
    __syncthreads();
    int acc = v;
#pragma unroll
    for (int off = 1; off < 1024; off <<= 1) {
        int t = (threadIdx.x >= off) ? sh[threadIdx.x - off] : 0;
        __syncthreads();
        acc += t;
        sh[threadIdx.x] = acc;
        __syncthreads();
    }
    if (threadIdx.x < nb) g_bsum[threadIdx.x] = acc - v;  // exclusive
}

__global__ void scan3_kernel(int n, int E) {
    int i = blockIdx.x * blockDim.x + threadIdx.x;
    if (i < n) {
        g_rowptr[i] += g_bsum[i / SCAN_T];
        g_dinv[i] = rsqrtf((float)(g_deg[i] + 1));
        g_cnt[i] = 0;
    }
    if (i == 0) g_rowptr[n] = E;
}

__global__ void fill_kernel(int E) {
    int e = blockIdx.x * blockDim.x + threadIdx.x;
    if (e >= E) return;
    int s = g_eidx[e];
    int d = g_eidx[E + e];
    int pos = g_rowptr[d] + atomicAdd(&g_cnt[d], 1);
    g_col[pos] = s;
    g_wsrc[pos] = g_dinv[s];
}

// ---------------- TF32 tensor-core GEMM (fp16 output) ----------------
template <int N, bool LAYER2>
__global__ __launch_bounds__(256)
void mma_gemm_kernel(const float* __restrict__ Ain, const float* __restrict__ W,
                     const float* __restrict__ bias, int M) {
    constexpr int K = 128, BM = 128, BK = 32;
    constexpr int ASTR = 36;
    constexpr int WSTR = N + 8;
    constexpr int NT = N / 8;

    __shared__ alignas(16) uint32_t As[BM][ASTR];
    __shared__ alignas(16) uint32_t Ws[BK][WSTR];
    __shared__ alignas(16) float bsh[K];

    const float* A = LAYER2 ? (const float*)g_agg1 : Ain;
    __half* C = LAYER2 ? g_h2h : g_h1h;

    const int tid = threadIdx.x;
    const int warp = tid >> 5;
    const int lane = tid & 31;
    const int gid = lane >> 2;
    const int tig = lane & 3;
    const int row0 = blockIdx.x * BM;

    if (LAYER2) {
        if (tid < K) bsh[tid] = bias[tid];
        __syncthreads();
    }

    float acc[NT][4];
#pragma unroll
    for (int nt = 0; nt < NT; nt++)
#pragma unroll
        for (int j = 0; j < 4; j++) acc[nt][j] = 0.0f;

    for (int k0 = 0; k0 < K; k0 += BK) {
#pragma unroll
        for (int i = 0; i < 4; i++) {
            int t = tid + i * 256;
            int r = t >> 3;
            int c4 = t & 7;
            int grow = row0 + r;
            float4 v = make_float4(0.f, 0.f, 0.f, 0.f);
            if (grow < M)
                v = *reinterpret_cast<const float4*>(&A[(size_t)grow * K + k0 + c4 * 4]);
            if constexpr (LAYER2) {
                int kk = k0 + c4 * 4;
                v.x = fmaxf(v.x + bsh[kk + 0], 0.f);
                v.y = fmaxf(v.y + bsh[kk + 1], 0.f);
                v.z = fmaxf(v.z + bsh[kk + 2], 0.f);
                v.w = fmaxf(v.w + bsh[kk + 3], 0.f);
            }
            uint4 u = make_uint4(f2tf(v.x), f2tf(v.y), f2tf(v.z), f2tf(v.w));
            *reinterpret_cast<uint4*>(&As[r][c4 * 4]) = u;
        }
#pragma unroll
        for (int i = 0; i < (BK * N) / (256 * 4); i++) {
            int t = tid + i * 256;
            int r = t / (N / 4);
            int c4 = t % (N / 4);
            float4 v = *reinterpret_cast<const float4*>(&W[(size_t)(k0 + r) * N + c4 * 4]);
            uint4 u = make_uint4(f2tf(v.x), f2tf(v.y), f2tf(v.z), f2tf(v.w));
            *reinterpret_cast<uint4*>(&Ws[r][c4 * 4]) = u;
        }
        __syncthreads();

#pragma unroll
        for (int ks = 0; ks < BK / 8; ks++) {
            int kk = ks * 8;
            uint32_t a0 = As[warp * 16 + gid][kk + tig];
            uint32_t a1 = As[warp * 16 + gid + 8][kk + tig];
            uint32_t a2 = As[warp * 16 + gid][kk + tig + 4];
            uint32_t a3 = As[warp * 16 + gid + 8][kk + tig + 4];
#pragma unroll
            for (int nt = 0; nt < NT; nt++) {
                uint32_t b0 = Ws[kk + tig][nt * 8 + gid];
                uint32_t b1 = Ws[kk + tig + 4][nt * 8 + gid];
                mma_tf32(acc[nt], a0, a1, a2, a3, b0, b1);
            }
        }
        __syncthreads();
    }

    int r0 = row0 + warp * 16 + gid;
    int r1 = r0 + 8;
#pragma unroll
    for (int nt = 0; nt < NT; nt++) {
        int col = nt * 8 + tig * 2;
        if (r0 < M)
            *reinterpret_cast<__half2*>(&C[(size_t)r0 * N + col]) =
                __floats2half2_rn(acc[nt][0], acc[nt][1]);
        if (r1 < M)
            *reinterpret_cast<__half2*>(&C[(size_t)r1 * N + col]) =
                __floats2half2_rn(acc[nt][2], acc[nt][3]);
    }
}

// ---------------- CSR gather aggregation (fp16 in, fp32 accum/out, MLP=8) ----------------
// One warp per dst node d. Inner loop runs fixed 8-wide rounds: 8 shfl-broadcast
// (idx,w) pairs, 8 independent row loads back-to-back (MLP=8), then FMAs.
// Slots past the degree carry w=0 / idx=0 -> zero-weight loads of row 0 (cached, free).
template <int F>
__global__ void gather_kernel(const float* __restrict__ b2, float* __restrict__ outp, int n) {
    int d = (blockIdx.x * blockDim.x + threadIdx.x) >> 5;
    if (d >= n) return;
    int lane = threadIdx.x & 31;
    const __half* h = (F == F1) ? (const __half*)g_h1h : (const __half*)g_h2h;
    float* outb = (F == F1) ? (float*)g_agg1 : outp;
    constexpr int PER = F / 32;  // 4 or 2 halves per lane

    int beg = g_rowptr[d];
    int end = g_rowptr[d + 1];
    float di = g_dinv[d];

    float a0 = 0.f, a1 = 0.f, a2 = 0.f, a3 = 0.f;
    for (int base = beg; base < end; base += 32) {
        int m = end - base;
        if (m > 32) m = 32;
        int idx = 0; float w = 0.f;
        if (lane < m) { idx = g_col[base + lane]; w = g_wsrc[base + lane]; }
        for (int j = 0; j < m; j += 8) {
            int ss[8]; float wv[8];
#pragma unroll
            for (int u = 0; u < 8; u++) {
                ss[u] = __shfl_sync(0xffffffffu, idx, j + u);
                wv[u] = __shfl_sync(0xffffffffu, w, j + u);
            }
            if (PER == 4) {
                uint2 uv[8];
#pragma unroll
                for (int u = 0; u < 8; u++)
                    uv[u] = *reinterpret_cast<const uint2*>(h + (size_t)ss[u] * F + lane * 4);
#pragma unroll
                for (int u = 0; u < 8; u++) {
                    float2 f0 = __half22float2(*reinterpret_cast<const __half2*>(&uv[u].x));
                    float2 f1 = __half22float2(*reinterpret_cast<const __half2*>(&uv[u].y));
                    a0 = fmaf(wv[u], f0.x, a0); a1 = fmaf(wv[u], f0.y, a1);
                    a2 = fmaf(wv[u], f1.x, a2); a3 = fmaf(wv[u], f1.y, a3);
                }
            } else {
                uint32_t uv[8];
#pragma unroll
                for (int u = 0; u < 8; u++)
                    uv[u] = *reinterpret_cast<const uint32_t*>(h + (size_t)ss[u] * F + lane * 2);
#pragma unroll
                for (int u = 0; u < 8; u++) {
                    float2 f0 = __half22float2(*reinterpret_cast<const __half2*>(&uv[u]));
                    a0 = fmaf(wv[u], f0.x, a0); a1 = fmaf(wv[u], f0.y, a1);
                }
            }
        }
    }

    // self-loop + scale (+ bias for layer 2)
    const __half* hd = h + (size_t)d * F + lane * PER;
    float* od = outb + (size_t)d * F + lane * PER;
    if (PER == 4) {
        uint2 u = *reinterpret_cast<const uint2*>(hd);
        float2 f0 = __half22float2(*reinterpret_cast<const __half2*>(&u.x));
        float2 f1 = __half22float2(*reinterpret_cast<const __half2*>(&u.y));
        float4 r;
        r.x = di * fmaf(di, f0.x, a0);
        r.y = di * fmaf(di, f0.y, a1);
        r.z = di * fmaf(di, f1.x, a2);
        r.w = di * fmaf(di, f1.y, a3);
        *reinterpret_cast<float4*>(od) = r;
    } else {
        uint32_t u = *reinterpret_cast<const uint32_t*>(hd);
        float2 f0 = __half22float2(*reinterpret_cast<const __half2*>(&u));
        float2 b = *reinterpret_cast<const float2*>(&b2[lane * PER]);
        float2 r;
        r.x = di * fmaf(di, f0.x, a0) + b.x;
        r.y = di * fmaf(di, f0.y, a1) + b.y;
        *reinterpret_cast<float2*>(od) = r;
    }
}

extern "C" void kernel_launch(void* const* d_in, const int* in_sizes, int n_in,
                              void* d_out, int out_size) {
    const float* x = (const float*)d_in[0];
    const void* ei = d_in[1];
    const float* W1 = (const float*)d_in[2];
    const float* b1 = (const float*)d_in[3];
    const float* W2 = (const float*)d_in[4];
    const float* b2 = (const float*)d_in[5];
    float* out = (float*)d_out;

    const int n = in_sizes[0] / F1;
    const int E = in_sizes[1] / 2;

    const int T = 256;
    // edge index: detect dtype (+ zero degrees), normalize to int32 (+ degree count fused)
    detect_kernel<<<256, T>>>(ei, E, n);
    convert_kernel<<<(2 * E + T - 1) / T, T>>>(ei, E, n);

    // CSR build: exclusive scan -> dinv -> bucket fill
    int nb = (n + SCAN_T - 1) / SCAN_T;
    scan1_kernel<<<nb, SCAN_T>>>(n);
    scan2_kernel<<<1, 1024>>>(nb);
    scan3_kernel<<<(n + T - 1) / T, T>>>(n, E);
    fill_kernel<<<(E + T - 1) / T, T>>>(E);

    // layer 1: g_h1h = x @ W1  (tf32 tensor cores, fp16 output)
    mma_gemm_kernel<128, false><<<(n + 127) / 128, 256>>>(x, W1, nullptr, n);
    // g_agg1 = D^-1/2 (A+I) D^-1/2 h1   (CSR gather, MLP=8)
    gather_kernel<F1><<<(n * 32 + T - 1) / T, T>>>(nullptr, nullptr, n);

    // layer 2: g_h2h = relu(g_agg1 + b1) @ W2  (bias+relu fused into A-load)
    mma_gemm_kernel<64, true><<<(n + 127) / 128, 256>>>(nullptr, W2, b1, n);
    // out = D^-1/2 (A+I) D^-1/2 h2 + b2   (CSR gather, writes d_out fp32)
    gather_kernel<F2><<<(n * 32 + T - 1) / T, T>>>(b2, out, n);
}

// round 12
// speedup vs baseline: 1.1171x; 1.1171x over previous
#include <cuda_runtime.h>
#include <cuda_fp16.h>
#include <cstdint>

#define MAXN 100000
#define MAXE 600000
#define F1 128
#define F2 64
#define SCAN_T 256

// Scratch: __device__ globals (allocation-free rule), referenced directly as symbols.
__device__ __half g_h1h[MAXN * F1];   // x @ W1 (fp16, gather operand)
__device__ __half g_agg1h[MAXN * F1]; // aggregated layer-1 (fp16, pre-bias/relu)
__device__ __half g_h2h[MAXN * F2];   // relu(agg1+b1) @ W2 (fp16, gather operand)
__device__ float  g_dinv[MAXN];       // rsqrt(deg+1)
__device__ int    g_eidx[2 * MAXE];   // normalized int32 edge index [src | dst]
__device__ int    g_is32 = 0;         // != 0 if raw edge buffer is int32 (idempotent across calls)
__device__ int    g_deg[MAXN];        // in-degree (excl self-loop)
__device__ int    g_rowptr[MAXN + 1]; // CSR row pointers (by dst)
__device__ int    g_cnt[MAXN];        // fill counters
__device__ int    g_col[MAXE];        // CSR: src per edge
__device__ float  g_wsrc[MAXE];       // CSR: dinv[src] per edge
__device__ int    g_bsum[1024];       // block sums for scan

// ---------------- tf32 helpers ----------------
__device__ __forceinline__ uint32_t f2tf(float f) {
    uint32_t u;
    asm("cvt.rna.tf32.f32 %0, %1;" : "=r"(u) : "f"(f));
    return u;
}
__device__ __forceinline__ void mma_tf32(float* c, uint32_t a0, uint32_t a1, uint32_t a2,
                                         uint32_t a3, uint32_t b0, uint32_t b1) {
    asm volatile(
        "mma.sync.aligned.m16n8k8.row.col.f32.tf32.tf32.f32 "
        "{%0,%1,%2,%3}, {%4,%5,%6,%7}, {%8,%9}, {%0,%1,%2,%3};"
        : "+f"(c[0]), "+f"(c[1]), "+f"(c[2]), "+f"(c[3])
        : "r"(a0), "r"(a1), "r"(a2), "r"(a3), "r"(b0), "r"(b1));
}

// ---------------- edge dtype detection (+ zero degree histogram) ----------------
__global__ void detect_kernel(const void* __restrict__ ei_raw, int E, int n) {
    const long long* p = (const long long*)ei_raw;
    int lbad = 0;
    for (int i = blockIdx.x * blockDim.x + threadIdx.x; i < E; i += gridDim.x * blockDim.x) {
        long long v = p[i];
        if (v < 0 || v >= (long long)n) lbad = 1;
    }
    for (int i = blockIdx.x * blockDim.x + threadIdx.x; i < n; i += gridDim.x * blockDim.x)
        g_deg[i] = 0;
    if (__syncthreads_or(lbad) && threadIdx.x == 0) atomicOr(&g_is32, 1);
}

// normalize edges to int32 + count in-degrees (dst half) in one pass
__global__ void convert_kernel(const void* __restrict__ ei_raw, int E, int n) {
    int i = blockIdx.x * blockDim.x + threadIdx.x;
    if (i >= 2 * E) return;
    int v;
    if (g_is32) v = ((const int*)ei_raw)[i];
    else        v = (int)((const long long*)ei_raw)[i];
    v = v < 0 ? 0 : (v >= n ? n - 1 : v);
    g_eidx[i] = v;
    if (i >= E) atomicAdd(&g_deg[v], 1);  // dst half
}

// ---------------- CSR build ----------------
__global__ void scan1_kernel(int n) {
    __shared__ int sh[SCAN_T];
    int i = blockIdx.x * SCAN_T + threadIdx.x;
    int v = (i < n) ? g_deg[i] : 0;
    sh[threadIdx.x] = v;
    __syncthreads();
    int acc = v;
#pragma unroll
    for (int off = 1; off < SCAN_T; off <<= 1) {
        int t = (threadIdx.x >= off) ? sh[threadIdx.x - off] : 0;
        __syncthreads();
        acc += t;
        sh[threadIdx.x] = acc;
        __syncthreads();
    }
    if (i < n) g_rowptr[i] = acc - v;  // exclusive
    if (threadIdx.x == SCAN_T - 1) g_bsum[blockIdx.x] = acc;
}

__global__ void scan2_kernel(int nb) {
    __shared__ int sh[1024];
    int v = (threadIdx.x < nb) ? g_bsum[threadIdx.x] : 0;
    sh[threadIdx.x] = v;
    __syncthreads();
    int acc = v;
#pragma unroll
    for (int off = 1; off < 1024; off <<= 1) {
        int t = (threadIdx.x >= off) ? sh[threadIdx.x - off] : 0;
        __syncthreads();
        acc += t;
        sh[threadIdx.x] = acc;
        __syncthreads();
    }
    if (threadIdx.x < nb) g_bsum[threadIdx.x] = acc - v;  // exclusive
}

__global__ void scan3_kernel(int n, int E) {
    int i = blockIdx.x * blockDim.x + threadIdx.x;
    if (i < n) {
        g_rowptr[i] += g_bsum[i / SCAN_T];
        g_dinv[i] = rsqrtf((float)(g_deg[i] + 1));
        g_cnt[i] = 0;
    }
    if (i == 0) g_rowptr[n] = E;
}

__global__ void fill_kernel(int E) {
    int e = blockIdx.x * blockDim.x + threadIdx.x;
    if (e >= E) return;
    int s = g_eidx[e];
    int d = g_eidx[E + e];
    int pos = g_rowptr[d] + atomicAdd(&g_cnt[d], 1);
    g_col[pos] = s;
    g_wsrc[pos] = g_dinv[s];
}

// ---------------- TF32 tensor-core GEMM (fp16 output) ----------------
// LAYER2=false: A=Ain (fp32 x), C=g_h1h, no activation
// LAYER2=true : A=g_agg1h (fp16 symbol), C=g_h2h, A-load fused with +b1,relu
template <int N, bool LAYER2>
__global__ __launch_bounds__(256)
void mma_gemm_kernel(const float* __restrict__ Ain, const float* __restrict__ W,
                     const float* __restrict__ bias, int M) {
    constexpr int K = 128, BM = 128, BK = 32;
    constexpr int ASTR = 36;
    constexpr int WSTR = N + 8;
    constexpr int NT = N / 8;

    __shared__ alignas(16) uint32_t As[BM][ASTR];
    __shared__ alignas(16) uint32_t Ws[BK][WSTR];
    __shared__ alignas(16) float bsh[K];

    __half* C = LAYER2 ? g_h2h : g_h1h;

    const int tid = threadIdx.x;
    const int warp = tid >> 5;
    const int lane = tid & 31;
    const int gid = lane >> 2;
    const int tig = lane & 3;
    const int row0 = blockIdx.x * BM;

    if (LAYER2) {
        if (tid < K) bsh[tid] = bias[tid];
        __syncthreads();
    }

    float acc[NT][4];
#pragma unroll
    for (int nt = 0; nt < NT; nt++)
#pragma unroll
        for (int j = 0; j < 4; j++) acc[nt][j] = 0.0f;

    for (int k0 = 0; k0 < K; k0 += BK) {
#pragma unroll
        for (int i = 0; i < 4; i++) {
            int t = tid + i * 256;
            int r = t >> 3;
            int c4 = t & 7;
            int grow = row0 + r;
            float4 v = make_float4(0.f, 0.f, 0.f, 0.f);
            if (grow < M) {
                if constexpr (LAYER2) {
                    uint2 u = *reinterpret_cast<const uint2*>(
                        &g_agg1h[(size_t)grow * K + k0 + c4 * 4]);
                    float2 f0 = __half22float2(*reinterpret_cast<const __half2*>(&u.x));
                    float2 f1 = __half22float2(*reinterpret_cast<const __half2*>(&u.y));
                    v = make_float4(f0.x, f0.y, f1.x, f1.y);
                } else {
                    v = *reinterpret_cast<const float4*>(&Ain[(size_t)grow * K + k0 + c4 * 4]);
                }
            }
            if constexpr (LAYER2) {
                int kk = k0 + c4 * 4;
                v.x = fmaxf(v.x + bsh[kk + 0], 0.f);
                v.y = fmaxf(v.y + bsh[kk + 1], 0.f);
                v.z = fmaxf(v.z + bsh[kk + 2], 0.f);
                v.w = fmaxf(v.w + bsh[kk + 3], 0.f);
            }
            uint4 u = make_uint4(f2tf(v.x), f2tf(v.y), f2tf(v.z), f2tf(v.w));
            *reinterpret_cast<uint4*>(&As[r][c4 * 4]) = u;
        }
#pragma unroll
        for (int i = 0; i < (BK * N) / (256 * 4); i++) {
            int t = tid + i * 256;
            int r = t / (N / 4);
            int c4 = t % (N / 4);
            float4 v = *reinterpret_cast<const float4*>(&W[(size_t)(k0 + r) * N + c4 * 4]);
            uint4 u = make_uint4(f2tf(v.x), f2tf(v.y), f2tf(v.z), f2tf(v.w));
            *reinterpret_cast<uint4*>(&Ws[r][c4 * 4]) = u;
        }
        __syncthreads();

#pragma unroll
        for (int ks = 0; ks < BK / 8; ks++) {
            int kk = ks * 8;
            uint32_t a0 = As[warp * 16 + gid][kk + tig];
            uint32_t a1 = As[warp * 16 + gid + 8][kk + tig];
            uint32_t a2 = As[warp * 16 + gid][kk + tig + 4];
            uint32_t a3 = As[warp * 16 + gid + 8][kk + tig + 4];
#pragma unroll
            for (int nt = 0; nt < NT; nt++) {
                uint32_t b0 = Ws[kk + tig][nt * 8 + gid];
                uint32_t b1 = Ws[kk + tig + 4][nt * 8 + gid];
                mma_tf32(acc[nt], a0, a1, a2, a3, b0, b1);
            }
        }
        __syncthreads();
    }

    int r0 = row0 + warp * 16 + gid;
    int r1 = r0 + 8;
#pragma unroll
    for (int nt = 0; nt < NT; nt++) {
        int col = nt * 8 + tig * 2;
        if (r0 < M)
            *reinterpret_cast<__half2*>(&C[(size_t)r0 * N + col]) =
                __floats2half2_rn(acc[nt][0], acc[nt][1]);
        if (r1 < M)
            *reinterpret_cast<__half2*>(&C[(size_t)r1 * N + col]) =
                __floats2half2_rn(acc[nt][2], acc[nt][3]);
    }
}

// ---------------- CSR gather aggregation (fp16 in, fp32 accum; serial inner loop) ----------------
// One warp per dst node d:
//   acc = sum_e wsrc[e] * h[col[e]];  out[d] = dinv[d]*acc + dinv[d]^2*h[d] (+ b2 layer 2)
// F==F1: h=g_h1h, out=g_agg1h (fp16, pre-bias/relu: GEMM2 fuses those).
// F==F2: h=g_h2h, out=outp (d_out fp32), + b2.
template <int F>
__global__ void gather_kernel(const float* __restrict__ b2, float* __restrict__ outp, int n) {
    int d = (blockIdx.x * blockDim.x + threadIdx.x) >> 5;
    if (d >= n) return;
    int lane = threadIdx.x & 31;
    const __half* h = (F == F1) ? (const __half*)g_h1h : (const __half*)g_h2h;
    constexpr int PER = F / 32;  // 4 or 2 halves per lane

    int beg = g_rowptr[d];
    int end = g_rowptr[d + 1];
    float di = g_dinv[d];

    float a0 = 0.f, a1 = 0.f, a2 = 0.f, a3 = 0.f;
    for (int base = beg; base < end; base += 32) {
        int m = end - base;
        if (m > 32) m = 32;
        int idx = 0; float w = 0.f;
        if (lane < m) { idx = g_col[base + lane]; w = g_wsrc[base + lane]; }
        for (int j = 0; j < m; j++) {
            int s = __shfl_sync(0xffffffffu, idx, j);
            float ww = __shfl_sync(0xffffffffu, w, j);
            const __half* hs = h + (size_t)s * F + lane * PER;
            if (PER == 4) {
                uint2 u = *reinterpret_cast<const uint2*>(hs);
                float2 f0 = __half22float2(*reinterpret_cast<const __half2*>(&u.x));
                float2 f1 = __half22float2(*reinterpret_cast<const __half2*>(&u.y));
                a0 = fmaf(ww, f0.x, a0); a1 = fmaf(ww, f0.y, a1);
                a2 = fmaf(ww, f1.x, a2); a3 = fmaf(ww, f1.y, a3);
            } else {
                uint32_t u = *reinterpret_cast<const uint32_t*>(hs);
                float2 f0 = __half22float2(*reinterpret_cast<const __half2*>(&u));
                a0 = fmaf(ww, f0.x, a0); a1 = fmaf(ww, f0.y, a1);
            }
        }
    }

    // self-loop + scale; layer1 -> fp16 agg, layer2 -> fp32 d_out + b2
    const __half* hd = h + (size_t)d * F + lane * PER;
    if (F == F1) {
        uint2 u = *reinterpret_cast<const uint2*>(hd);
        float2 f0 = __half22float2(*reinterpret_cast<const __half2*>(&u.x));
        float2 f1 = __half22float2(*reinterpret_cast<const __half2*>(&u.y));
        float rx = di * fmaf(di, f0.x, a0);
        float ry = di * fmaf(di, f0.y, a1);
        float rz = di * fmaf(di, f1.x, a2);
        float rw = di * fmaf(di, f1.y, a3);
        uint2 o;
        *reinterpret_cast<__half2*>(&o.x) = __floats2half2_rn(rx, ry);
        *reinterpret_cast<__half2*>(&o.y) = __floats2half2_rn(rz, rw);
        *reinterpret_cast<uint2*>(&g_agg1h[(size_t)d * F + lane * PER]) = o;
    } else {
        uint32_t u = *reinterpret_cast<const uint32_t*>(hd);
        float2 f0 = __half22float2(*reinterpret_cast<const __half2*>(&u));
        float2 b = *reinterpret_cast<const float2*>(&b2[lane * PER]);
        float2 r;
        r.x = di * fmaf(di, f0.x, a0) + b.x;
        r.y = di * fmaf(di, f0.y, a1) + b.y;
        *reinterpret_cast<float2*>(&outp[(size_t)d * F + lane * PER]) = r;
    }
}

extern "C" void kernel_launch(void* const* d_in, const int* in_sizes, int n_in,
                              void* d_out, int out_size) {
    const float* x = (const float*)d_in[0];
    const void* ei = d_in[1];
    const float* W1 = (const float*)d_in[2];
    const float* b1 = (const float*)d_in[3];
    const float* W2 = (const float*)d_in[4];
    const float* b2 = (const float*)d_in[5];
    float* out = (float*)d_out;

    const int n = in_sizes[0] / F1;
    const int E = in_sizes[1] / 2;

    const int T = 256;
    // edge index: detect dtype (+ zero degrees), normalize to int32 (+ degree count fused)
    detect_kernel<<<256, T>>>(ei, E, n);
    convert_kernel<<<(2 * E + T - 1) / T, T>>>(ei, E, n);

    // CSR build: exclusive scan -> dinv -> bucket fill
    int nb = (n + SCAN_T - 1) / SCAN_T;
    scan1_kernel<<<nb, SCAN_T>>>(n);
    scan2_kernel<<<1, 1024>>>(nb);
    scan3_kernel<<<(n + T - 1) / T, T>>>(n, E);
    fill_kernel<<<(E + T - 1) / T, T>>>(E);

    // layer 1: g_h1h = x @ W1  (tf32 tensor cores, fp16 output)
    mma_gemm_kernel<128, false><<<(n + 127) / 128, 256>>>(x, W1, nullptr, n);
    // g_agg1h = D^-1/2 (A+I) D^-1/2 h1   (CSR gather, fp16 out)
    gather_kernel<F1><<<(n * 32 + T - 1) / T, T>>>(nullptr, nullptr, n);

    // layer 2: g_h2h = relu(g_agg1h + b1) @ W2  (bias+relu fused into fp16 A-load)
    mma_gemm_kernel<64, true><<<(n + 127) / 128, 256>>>(nullptr, W2, b1, n);
    // out = D^-1/2 (A+I) D^-1/2 h2 + b2   (CSR gather, writes d_out fp32)
    gather_kernel<F2><<<(n * 32 + T - 1) / T, T>>>(b2, out, n);
}

// round 14
// speedup vs baseline: 1.1454x; 1.0253x over previous
#include <cuda_runtime.h>
#include <cuda_fp16.h>
#include <cstdint>

#define MAXN 100000
#define MAXE 600000
#define F1 128
#define F2 64
#define SCAN_T 256

// Scratch: __device__ globals (allocation-free rule), referenced directly as symbols.
__device__ __half g_h1h[MAXN * F1];   // x @ W1 (fp16, gather operand)
__device__ __half g_agg1h[MAXN * F1]; // aggregated layer-1 (fp16, pre-bias/relu)
__device__ __half g_h2h[MAXN * F2];   // relu(agg1+b1) @ W2 (fp16, gather operand)
__device__ float  g_dinv[MAXN];       // rsqrt(deg+1)
__device__ int    g_eidx[2 * MAXE];   // normalized int32 edge index [src | dst]
__device__ int    g_is32 = 0;         // != 0 if raw edge buffer is int32 (idempotent across calls)
__device__ int    g_deg[MAXN];        // in-degree (excl self-loop)
__device__ int    g_rowptr[MAXN + 1]; // CSR row pointers (by dst)
__device__ int    g_cnt[MAXN];        // fill counters
__device__ int    g_col[MAXE];        // CSR: src per edge
__device__ float  g_wsrc[MAXE];       // CSR: dinv[src] per edge
__device__ int    g_bsum[1024];       // block sums for scan

// ---------------- tf32 helpers ----------------
__device__ __forceinline__ uint32_t f2tf(float f) {
    uint32_t u;
    asm("cvt.rna.tf32.f32 %0, %1;" : "=r"(u) : "f"(f));
    return u;
}
__device__ __forceinline__ void mma_tf32(float* c, uint32_t a0, uint32_t a1, uint32_t a2,
                                         uint32_t a3, uint32_t b0, uint32_t b1) {
    asm volatile(
        "mma.sync.aligned.m16n8k8.row.col.f32.tf32.tf32.f32 "
        "{%0,%1,%2,%3}, {%4,%5,%6,%7}, {%8,%9}, {%0,%1,%2,%3};"
        : "+f"(c[0]), "+f"(c[1]), "+f"(c[2]), "+f"(c[3])
        : "r"(a0), "r"(a1), "r"(a2), "r"(a3), "r"(b0), "r"(b1));
}

// ---------------- edge dtype detection (sampled) + zero degree histogram ----------------
// Block 0 samples ~512 spread slots of the buffer interpreted as int64. True int64
// data: every sample in [0, n). int32 data misread as int64: a sample is in-range
// only if its high word (uniform in [0,n)) is exactly 0 (p ~ 1e-5) -> detection is
// effectively certain. All blocks zero the degree histogram (grid-stride).
__global__ void detect_kernel(const void* __restrict__ ei_raw, int E, int n) {
    for (int i = blockIdx.x * blockDim.x + threadIdx.x; i < n; i += gridDim.x * blockDim.x)
        g_deg[i] = 0;
    if (blockIdx.x == 0) {
        const long long* p = (const long long*)ei_raw;
        int stride = E / 512; if (stride < 1) stride = 1;
        int lbad = 0;
        for (int k = threadIdx.x; k < 512; k += blockDim.x) {
            int i = k * stride; if (i >= E) i = E - 1;
            long long v = p[i];
            if (v < 0 || v >= (long long)n) lbad = 1;
        }
        if (__syncthreads_or(lbad) && threadIdx.x == 0) atomicOr(&g_is32, 1);
    }
}

// normalize edges to int32 + count in-degrees (dst half) in one pass
__global__ void convert_kernel(const void* __restrict__ ei_raw, int E, int n) {
    int i = blockIdx.x * blockDim.x + threadIdx.x;
    if (i >= 2 * E) return;
    int v;
    if (g_is32) v = ((const int*)ei_raw)[i];
    else        v = (int)((const long long*)ei_raw)[i];
    v = v < 0 ? 0 : (v >= n ? n - 1 : v);
    g_eidx[i] = v;
    if (i >= E) atomicAdd(&g_deg[v], 1);  // dst half
}

// ---------------- CSR build ----------------
// pass 1: per-block exclusive scan of g_deg -> g_rowptr (local), block sums -> g_bsum
__global__ void scan1_kernel(int n) {
    __shared__ int sh[SCAN_T];
    int i = blockIdx.x * SCAN_T + threadIdx.x;
    int v = (i < n) ? g_deg[i] : 0;
    sh[threadIdx.x] = v;
    __syncthreads();
    int acc = v;
#pragma unroll
    for (int off = 1; off < SCAN_T; off <<= 1) {
        int t = (threadIdx.x >= off) ? sh[threadIdx.x - off] : 0;
        __syncthreads();
        acc += t;
        sh[threadIdx.x] = acc;
        __syncthreads();
    }
    if (i < n) g_rowptr[i] = acc - v;  // exclusive
    if (threadIdx.x == SCAN_T - 1) g_bsum[blockIdx.x] = acc;
}

// pass 2 (merged): block b reduces g_bsum[0..b-1] for its offset, then applies it,
// computes dinv = rsqrt(deg+1), zeroes fill counters, sets rowptr[n]=E.
__global__ void scan2_kernel(int n, int E) {
    __shared__ int sh[SCAN_T];
    int b = blockIdx.x;
    int partial = 0;
    for (int j = threadIdx.x; j < b; j += SCAN_T) partial += g_bsum[j];
    sh[threadIdx.x] = partial;
    __syncthreads();
#pragma unroll
    for (int off = SCAN_T / 2; off > 0; off >>= 1) {
        if (threadIdx.x < off) sh[threadIdx.x] += sh[threadIdx.x + off];
        __syncthreads();
    }
    int offset = sh[0];
    int i = b * SCAN_T + threadIdx.x;
    if (i < n) {
        g_rowptr[i] += offset;
        g_dinv[i] = rsqrtf((float)(g_deg[i] + 1));
        g_cnt[i] = 0;
    }
    if (b == 0 && threadIdx.x == 0) g_rowptr[n] = E;
}

// fill CSR buckets: col = src, wsrc = dinv[src]
__global__ void fill_kernel(int E) {
    int e = blockIdx.x * blockDim.x + threadIdx.x;
    if (e >= E) return;
    int s = g_eidx[e];
    int d = g_eidx[E + e];
    int pos = g_rowptr[d] + atomicAdd(&g_cnt[d], 1);
    g_col[pos] = s;
    g_wsrc[pos] = g_dinv[s];
}

// ---------------- TF32 tensor-core GEMM (fp16 output) ----------------
// LAYER2=false: A=Ain (fp32 x), C=g_h1h, no activation
// LAYER2=true : A=g_agg1h (fp16 symbol), C=g_h2h, A-load fused with +b1,relu
template <int N, bool LAYER2>
__global__ __launch_bounds__(256)
void mma_gemm_kernel(const float* __restrict__ Ain, const float* __restrict__ W,
                     const float* __restrict__ bias, int M) {
    constexpr int K = 128, BM = 128, BK = 32;
    constexpr int ASTR = 36;
    constexpr int WSTR = N + 8;
    constexpr int NT = N / 8;

    __shared__ alignas(16) uint32_t As[BM][ASTR];
    __shared__ alignas(16) uint32_t Ws[BK][WSTR];
    __shared__ alignas(16) float bsh[K];

    __half* C = LAYER2 ? g_h2h : g_h1h;

    const int tid = threadIdx.x;
    const int warp = tid >> 5;
    const int lane = tid & 31;
    const int gid = lane >> 2;
    const int tig = lane & 3;
    const int row0 = blockIdx.x * BM;

    if (LAYER2) {
        if (tid < K) bsh[tid] = bias[tid];
        __syncthreads();
    }

    float acc[NT][4];
#pragma unroll
    for (int nt = 0; nt < NT; nt++)
#pragma unroll
        for (int j = 0; j < 4; j++) acc[nt][j] = 0.0f;

    for (int k0 = 0; k0 < K; k0 += BK) {
#pragma unroll
        for (int i = 0; i < 4; i++) {
            int t = tid + i * 256;
            int r = t >> 3;
            int c4 = t & 7;
            int grow = row0 + r;
            float4 v = make_float4(0.f, 0.f, 0.f, 0.f);
            if (grow < M) {
                if constexpr (LAYER2) {
                    uint2 u = *reinterpret_cast<const uint2*>(
                        &g_agg1h[(size_t)grow * K + k0 + c4 * 4]);
                    float2 f0 = __half22float2(*reinterpret_cast<const __half2*>(&u.x));
                    float2 f1 = __half22float2(*reinterpret_cast<const __half2*>(&u.y));
                    v = make_float4(f0.x, f0.y, f1.x, f1.y);
                } else {
                    v = *reinterpret_cast<const float4*>(&Ain[(size_t)grow * K + k0 + c4 * 4]);
                }
            }
            if constexpr (LAYER2) {
                int kk = k0 + c4 * 4;
                v.x = fmaxf(v.x + bsh[kk + 0], 0.f);
                v.y = fmaxf(v.y + bsh[kk + 1], 0.f);
                v.z = fmaxf(v.z + bsh[kk + 2], 0.f);
                v.w = fmaxf(v.w + bsh[kk + 3], 0.f);
            }
            uint4 u = make_uint4(f2tf(v.x), f2tf(v.y), f2tf(v.z), f2tf(v.w));
            *reinterpret_cast<uint4*>(&As[r][c4 * 4]) = u;
        }
#pragma unroll
        for (int i = 0; i < (BK * N) / (256 * 4); i++) {
            int t = tid + i * 256;
            int r = t / (N / 4);
            int c4 = t % (N / 4);
            float4 v = *reinterpret_cast<const float4*>(&W[(size_t)(k0 + r) * N + c4 * 4]);
            uint4 u = make_uint4(f2tf(v.x), f2tf(v.y), f2tf(v.z), f2tf(v.w));
            *reinterpret_cast<uint4*>(&Ws[r][c4 * 4]) = u;
        }
        __syncthreads();

#pragma unroll
        for (int ks = 0; ks < BK / 8; ks++) {
            int kk = ks * 8;
            uint32_t a0 = As[warp * 16 + gid][kk + tig];
            uint32_t a1 = As[warp * 16 + gid + 8][kk + tig];
            uint32_t a2 = As[warp * 16 + gid][kk + tig + 4];
            uint32_t a3 = As[warp * 16 + gid + 8][kk + tig + 4];
#pragma unroll
            for (int nt = 0; nt < NT; nt++) {
                uint32_t b0 = Ws[kk + tig][nt * 8 + gid];
                uint32_t b1 = Ws[kk + tig + 4][nt * 8 + gid];
                mma_tf32(acc[nt], a0, a1, a2, a3, b0, b1);
            }
        }
        __syncthreads();
    }

    int r0 = row0 + warp * 16 + gid;
    int r1 = r0 + 8;
#pragma unroll
    for (int nt = 0; nt < NT; nt++) {
        int col = nt * 8 + tig * 2;
        if (r0 < M)
            *reinterpret_cast<__half2*>(&C[(size_t)r0 * N + col]) =
                __floats2half2_rn(acc[nt][0], acc[nt][1]);
        if (r1 < M)
            *reinterpret_cast<__half2*>(&C[(size_t)r1 * N + col]) =
                __floats2half2_rn(acc[nt][2], acc[nt][3]);
    }
}

// ---------------- CSR gather aggregation (fp16 in, fp32 accum; serial inner loop) ----------------
// One warp per dst node d:
//   acc = sum_e wsrc[e] * h[col[e]];  out[d] = dinv[d]*acc + dinv[d]^2*h[d] (+ b2 layer 2)
// F==F1: h=g_h1h, out=g_agg1h (fp16, pre-bias/relu: GEMM2 fuses those).
// F==F2: h=g_h2h, out=outp (d_out fp32), + b2.
template <int F>
__global__ void gather_kernel(const float* __restrict__ b2, float* __restrict__ outp, int n) {
    int d = (blockIdx.x * blockDim.x + threadIdx.x) >> 5;
    if (d >= n) return;
    int lane = threadIdx.x & 31;
    const __half* h = (F == F1) ? (const __half*)g_h1h : (const __half*)g_h2h;
    constexpr int PER = F / 32;  // 4 or 2 halves per lane

    int beg = g_rowptr[d];
    int end = g_rowptr[d + 1];
    float di = g_dinv[d];

    float a0 = 0.f, a1 = 0.f, a2 = 0.f, a3 = 0.f;
    for (int base = beg; base < end; base += 32) {
        int m = end - base;
        if (m > 32) m = 32;
        int idx = 0; float w = 0.f;
        if (lane < m) { idx = g_col[base + lane]; w = g_wsrc[base + lane]; }
        for (int j = 0; j < m; j++) {
            int s = __shfl_sync(0xffffffffu, idx, j);
            float ww = __shfl_sync(0xffffffffu, w, j);
            const __half* hs = h + (size_t)s * F + lane * PER;
            if (PER == 4) {
                uint2 u = *reinterpret_cast<const uint2*>(hs);
                float2 f0 = __half22float2(*reinterpret_cast<const __half2*>(&u.x));
                float2 f1 = __half22float2(*reinterpret_cast<const __half2*>(&u.y));
                a0 = fmaf(ww, f0.x, a0); a1 = fmaf(ww, f0.y, a1);
                a2 = fmaf(ww, f1.x, a2); a3 = fmaf(ww, f1.y, a3);
            } else {
                uint32_t u = *reinterpret_cast<const uint32_t*>(hs);
                float2 f0 = __half22float2(*reinterpret_cast<const __half2*>(&u));
                a0 = fmaf(ww, f0.x, a0); a1 = fmaf(ww, f0.y, a1);
            }
        }
    }

    // self-loop + scale; layer1 -> fp16 agg, layer2 -> fp32 d_out + b2
    const __half* hd = h + (size_t)d * F + lane * PER;
    if (F == F1) {
        uint2 u = *reinterpret_cast<const uint2*>(hd);
        float2 f0 = __half22float2(*reinterpret_cast<const __half2*>(&u.x));
        float2 f1 = __half22float2(*reinterpret_cast<const __half2*>(&u.y));
        float rx = di * fmaf(di, f0.x, a0);
        float ry = di * fmaf(di, f0.y, a1);
        float rz = di * fmaf(di, f1.x, a2);
        float rw = di * fmaf(di, f1.y, a3);
        uint2 o;
        *reinterpret_cast<__half2*>(&o.x) = __floats2half2_rn(rx, ry);
        *reinterpret_cast<__half2*>(&o.y) = __floats2half2_rn(rz, rw);
        *reinterpret_cast<uint2*>(&g_agg1h[(size_t)d * F + lane * PER]) = o;
    } else {
        uint32_t u = *reinterpret_cast<const uint32_t*>(hd);
        float2 f0 = __half22float2(*reinterpret_cast<const __half2*>(&u));
        float2 b = *reinterpret_cast<const float2*>(&b2[lane * PER]);
        float2 r;
        r.x = di * fmaf(di, f0.x, a0) + b.x;
        r.y = di * fmaf(di, f0.y, a1) + b.y;
        *reinterpret_cast<float2*>(&outp[(size_t)d * F + lane * PER]) = r;
    }
}

extern "C" void kernel_launch(void* const* d_in, const int* in_sizes, int n_in,
                              void* d_out, int out_size) {
    const float* x = (const float*)d_in[0];
    const void* ei = d_in[1];
    const float* W1 = (const float*)d_in[2];
    const float* b1 = (const float*)d_in[3];
    const float* W2 = (const float*)d_in[4];
    const float* b2 = (const float*)d_in[5];
    float* out = (float*)d_out;

    const int n = in_sizes[0] / F1;
    const int E = in_sizes[1] / 2;

    const int T = 256;
    // edge index: sampled dtype detect (+ zero degrees), normalize (+ degree count fused)
    detect_kernel<<<256, T>>>(ei, E, n);
    convert_kernel<<<(2 * E + T - 1) / T, T>>>(ei, E, n);

    // CSR build: block-local scan -> offset-reduce (+dinv, cnt, rowptr[n]) -> bucket fill
    int nb = (n + SCAN_T - 1) / SCAN_T;
    scan1_kernel<<<nb, SCAN_T>>>(n);
    scan2_kernel<<<nb, SCAN_T>>>(n, E);
    fill_kernel<<<(E + T - 1) / T, T>>>(E);

    // layer 1: g_h1h = x @ W1  (tf32 tensor cores, fp16 output)
    mma_gemm_kernel<128, false><<<(n + 127) / 128, 256>>>(x, W1, nullptr, n);
    // g_agg1h = D^-1/2 (A+I) D^-1/2 h1   (CSR gather, fp16 out)
    gather_kernel<F1><<<(n * 32 + T - 1) / T, T>>>(nullptr, nullptr, n);

    // layer 2: g_h2h = relu(g_agg1h + b1) @ W2  (bias+relu fused into fp16 A-load)
    mma_gemm_kernel<64, true><<<(n + 127) / 128, 256>>>(nullptr, W2, b1, n);
    // out = D^-1/2 (A+I) D^-1/2 h2 + b2   (CSR gather, writes d_out fp32)
    gather_kernel<F2><<<(n * 32 + T - 1) / T, T>>>(b2, out, n);
}

// round 15
// speedup vs baseline: 1.2161x; 1.0617x over previous
#include <cuda_runtime.h>
#include <cuda_fp16.h>
#include <cstdint>

#define MAXN 100000
#define MAXE 600000
#define F1 128
#define F2 64
#define SCAN_T 256

// Scratch: __device__ globals (allocation-free rule), referenced directly as symbols.
__device__ __half g_h1h[MAXN * F1];   // x @ W1 (fp16, gather operand)
__device__ __half g_agg1h[MAXN * F1]; // aggregated layer-1 (fp16, pre-bias/relu)
__device__ __half g_h2h[MAXN * F2];   // relu(agg1+b1) @ W2 (fp16, gather operand)
__device__ float  g_dinv[MAXN];       // rsqrt(deg+1)
__device__ int    g_eidx[2 * MAXE];   // normalized int32 edge index [src | dst]
__device__ int    g_is32 = 0;         // != 0 if raw edge buffer is int32 (idempotent across calls)
__device__ int    g_deg[MAXN];        // in-degree (excl self-loop)
__device__ int    g_rowptr[MAXN + 1]; // CSR row pointers (by dst)
__device__ int    g_cnt[MAXN];        // fill counters
__device__ int    g_col[MAXE];        // CSR: src per edge
__device__ float  g_wsrc[MAXE];       // CSR: dinv[src] per edge
__device__ int    g_bsum[1024];       // block sums for scan

// ---------------- tf32 helpers ----------------
__device__ __forceinline__ uint32_t f2tf(float f) {
    uint32_t u;
    asm("cvt.rna.tf32.f32 %0, %1;" : "=r"(u) : "f"(f));
    return u;
}
__device__ __forceinline__ void mma_tf32(float* c, uint32_t a0, uint32_t a1, uint32_t a2,
                                         uint32_t a3, uint32_t b0, uint32_t b1) {
    asm volatile(
        "mma.sync.aligned.m16n8k8.row.col.f32.tf32.tf32.f32 "
        "{%0,%1,%2,%3}, {%4,%5,%6,%7}, {%8,%9}, {%0,%1,%2,%3};"
        : "+f"(c[0]), "+f"(c[1]), "+f"(c[2]), "+f"(c[3])
        : "r"(a0), "r"(a1), "r"(a2), "r"(a3), "r"(b0), "r"(b1));
}

// ---------------- edge dtype detection (sampled) + zero degree histogram ----------------
__global__ void detect_kernel(const void* __restrict__ ei_raw, int E, int n) {
    for (int i = blockIdx.x * blockDim.x + threadIdx.x; i < n; i += gridDim.x * blockDim.x)
        g_deg[i] = 0;
    if (blockIdx.x == 0) {
        const long long* p = (const long long*)ei_raw;
        int stride = E / 512; if (stride < 1) stride = 1;
        int lbad = 0;
        for (int k = threadIdx.x; k < 512; k += blockDim.x) {
            int i = k * stride; if (i >= E) i = E - 1;
            long long v = p[i];
            if (v < 0 || v >= (long long)n) lbad = 1;
        }
        if (__syncthreads_or(lbad) && threadIdx.x == 0) atomicOr(&g_is32, 1);
    }
}

// normalize edges to int32 + count in-degrees (dst half) in one pass
__global__ void convert_kernel(const void* __restrict__ ei_raw, int E, int n) {
    int i = blockIdx.x * blockDim.x + threadIdx.x;
    if (i >= 2 * E) return;
    int v;
    if (g_is32) v = ((const int*)ei_raw)[i];
    else        v = (int)((const long long*)ei_raw)[i];
    v = v < 0 ? 0 : (v >= n ? n - 1 : v);
    g_eidx[i] = v;
    if (i >= E) atomicAdd(&g_deg[v], 1);  // dst half
}

// ---------------- CSR build ----------------
__global__ void scan1_kernel(int n) {
    __shared__ int sh[SCAN_T];
    int i = blockIdx.x * SCAN_T + threadIdx.x;
    int v = (i < n) ? g_deg[i] : 0;
    sh[threadIdx.x] = v;
    __syncthreads();
    int acc = v;
#pragma unroll
    for (int off = 1; off < SCAN_T; off <<= 1) {
        int t = (threadIdx.x >= off) ? sh[threadIdx.x - off] : 0;
        __syncthreads();
        acc += t;
        sh[threadIdx.x] = acc;
        __syncthreads();
    }
    if (i < n) g_rowptr[i] = acc - v;  // exclusive
    if (threadIdx.x == SCAN_T - 1) g_bsum[blockIdx.x] = acc;
}

// block b reduces g_bsum[0..b-1] for its offset, then applies it,
// computes dinv = rsqrt(deg+1), zeroes fill counters, sets rowptr[n]=E.
__global__ void scan2_kernel(int n, int E) {
    __shared__ int sh[SCAN_T];
    int b = blockIdx.x;
    int partial = 0;
    for (int j = threadIdx.x; j < b; j += SCAN_T) partial += g_bsum[j];
    sh[threadIdx.x] = partial;
    __syncthreads();
#pragma unroll
    for (int off = SCAN_T / 2; off > 0; off >>= 1) {
        if (threadIdx.x < off) sh[threadIdx.x] += sh[threadIdx.x + off];
        __syncthreads();
    }
    int offset = sh[0];
    int i = b * SCAN_T + threadIdx.x;
    if (i < n) {
        g_rowptr[i] += offset;
        g_dinv[i] = rsqrtf((float)(g_deg[i] + 1));
        g_cnt[i] = 0;
    }
    if (b == 0 && threadIdx.x == 0) g_rowptr[n] = E;
}

// fill CSR buckets: col = src, wsrc = dinv[src]
__global__ void fill_kernel(int E) {
    int e = blockIdx.x * blockDim.x + threadIdx.x;
    if (e >= E) return;
    int s = g_eidx[e];
    int d = g_eidx[E + e];
    int pos = g_rowptr[d] + atomicAdd(&g_cnt[d], 1);
    g_col[pos] = s;
    g_wsrc[pos] = g_dinv[s];
}

// ---------------- TF32 tensor-core GEMM (fp16 output) ----------------
// LAYER2=false: A=Ain (fp32 x), C=g_h1h, no activation
// LAYER2=true : A=g_agg1h (fp16 symbol), C=g_h2h, A-load fused with +b1,relu
template <int N, bool LAYER2>
__global__ __launch_bounds__(256)
void mma_gemm_kernel(const float* __restrict__ Ain, const float* __restrict__ W,
                     const float* __restrict__ bias, int M) {
    constexpr int K = 128, BM = 128, BK = 32;
    constexpr int ASTR = 36;
    constexpr int WSTR = N + 8;
    constexpr int NT = N / 8;

    __shared__ alignas(16) uint32_t As[BM][ASTR];
    __shared__ alignas(16) uint32_t Ws[BK][WSTR];
    __shared__ alignas(16) float bsh[K];

    __half* C = LAYER2 ? g_h2h : g_h1h;

    const int tid = threadIdx.x;
    const int warp = tid >> 5;
    const int lane = tid & 31;
    const int gid = lane >> 2;
    const int tig = lane & 3;
    const int row0 = blockIdx.x * BM;

    if (LAYER2) {
        if (tid < K) bsh[tid] = bias[tid];
        __syncthreads();
    }

    float acc[NT][4];
#pragma unroll
    for (int nt = 0; nt < NT; nt++)
#pragma unroll
        for (int j = 0; j < 4; j++) acc[nt][j] = 0.0f;

    for (int k0 = 0; k0 < K; k0 += BK) {
#pragma unroll
        for (int i = 0; i < 4; i++) {
            int t = tid + i * 256;
            int r = t >> 3;
            int c4 = t & 7;
            int grow = row0 + r;
            float4 v = make_float4(0.f, 0.f, 0.f, 0.f);
            if (grow < M) {
                if constexpr (LAYER2) {
                    uint2 u = *reinterpret_cast<const uint2*>(
                        &g_agg1h[(size_t)grow * K + k0 + c4 * 4]);
                    float2 f0 = __half22float2(*reinterpret_cast<const __half2*>(&u.x));
                    float2 f1 = __half22float2(*reinterpret_cast<const __half2*>(&u.y));
                    v = make_float4(f0.x, f0.y, f1.x, f1.y);
                } else {
                    v = *reinterpret_cast<const float4*>(&Ain[(size_t)grow * K + k0 + c4 * 4]);
                }
            }
            if constexpr (LAYER2) {
                int kk = k0 + c4 * 4;
                v.x = fmaxf(v.x + bsh[kk + 0], 0.f);
                v.y = fmaxf(v.y + bsh[kk + 1], 0.f);
                v.z = fmaxf(v.z + bsh[kk + 2], 0.f);
                v.w = fmaxf(v.w + bsh[kk + 3], 0.f);
            }
            uint4 u = make_uint4(f2tf(v.x), f2tf(v.y), f2tf(v.z), f2tf(v.w));
            *reinterpret_cast<uint4*>(&As[r][c4 * 4]) = u;
        }
#pragma unroll
        for (int i = 0; i < (BK * N) / (256 * 4); i++) {
            int t = tid + i * 256;
            int r = t / (N / 4);
            int c4 = t % (N / 4);
            float4 v = *reinterpret_cast<const float4*>(&W[(size_t)(k0 + r) * N + c4 * 4]);
            uint4 u = make_uint4(f2tf(v.x), f2tf(v.y), f2tf(v.z), f2tf(v.w));
            *reinterpret_cast<uint4*>(&Ws[r][c4 * 4]) = u;
        }
        __syncthreads();

#pragma unroll
        for (int ks = 0; ks < BK / 8; ks++) {
            int kk = ks * 8;
            uint32_t a0 = As[warp * 16 + gid][kk + tig];
            uint32_t a1 = As[warp * 16 + gid + 8][kk + tig];
            uint32_t a2 = As[warp * 16 + gid][kk + tig + 4];
            uint32_t a3 = As[warp * 16 + gid + 8][kk + tig + 4];
#pragma unroll
            for (int nt = 0; nt < NT; nt++) {
                uint32_t b0 = Ws[kk + tig][nt * 8 + gid];
                uint32_t b1 = Ws[kk + tig + 4][nt * 8 + gid];
                mma_tf32(acc[nt], a0, a1, a2, a3, b0, b1);
            }
        }
        __syncthreads();
    }

    int r0 = row0 + warp * 16 + gid;
    int r1 = r0 + 8;
#pragma unroll
    for (int nt = 0; nt < NT; nt++) {
        int col = nt * 8 + tig * 2;
        if (r0 < M)
            *reinterpret_cast<__half2*>(&C[(size_t)r0 * N + col]) =
                __floats2half2_rn(acc[nt][0], acc[nt][1]);
        if (r1 < M)
            *reinterpret_cast<__half2*>(&C[(size_t)r1 * N + col]) =
                __floats2half2_rn(acc[nt][2], acc[nt][3]);
    }
}

// ---------------- CSR gather aggregation (fp16 in, fp32 accum; serial inner loop) ----------------
template <int F>
__global__ void gather_kernel(const float* __restrict__ b2, float* __restrict__ outp, int n) {
    int d = (blockIdx.x * blockDim.x + threadIdx.x) >> 5;
    if (d >= n) return;
    int lane = threadIdx.x & 31;
    const __half* h = (F == F1) ? (const __half*)g_h1h : (const __half*)g_h2h;
    constexpr int PER = F / 32;  // 4 or 2 halves per lane

    int beg = g_rowptr[d];
    int end = g_rowptr[d + 1];
    float di = g_dinv[d];

    float a0 = 0.f, a1 = 0.f, a2 = 0.f, a3 = 0.f;
    for (int base = beg; base < end; base += 32) {
        int m = end - base;
        if (m > 32) m = 32;
        int idx = 0; float w = 0.f;
        if (lane < m) { idx = g_col[base + lane]; w = g_wsrc[base + lane]; }
        for (int j = 0; j < m; j++) {
            int s = __shfl_sync(0xffffffffu, idx, j);
            float ww = __shfl_sync(0xffffffffu, w, j);
            const __half* hs = h + (size_t)s * F + lane * PER;
            if (PER == 4) {
                uint2 u = *reinterpret_cast<const uint2*>(hs);
                float2 f0 = __half22float2(*reinterpret_cast<const __half2*>(&u.x));
                float2 f1 = __half22float2(*reinterpret_cast<const __half2*>(&u.y));
                a0 = fmaf(ww, f0.x, a0); a1 = fmaf(ww, f0.y, a1);
                a2 = fmaf(ww, f1.x, a2); a3 = fmaf(ww, f1.y, a3);
            } else {
                uint32_t u = *reinterpret_cast<const uint32_t*>(hs);
                float2 f0 = __half22float2(*reinterpret_cast<const __half2*>(&u));
                a0 = fmaf(ww, f0.x, a0); a1 = fmaf(ww, f0.y, a1);
            }
        }
    }

    // self-loop + scale; layer1 -> fp16 agg, layer2 -> fp32 d_out + b2
    const __half* hd = h + (size_t)d * F + lane * PER;
    if (F == F1) {
        uint2 u = *reinterpret_cast<const uint2*>(hd);
        float2 f0 = __half22float2(*reinterpret_cast<const __half2*>(&u.x));
        float2 f1 = __half22float2(*reinterpret_cast<const __half2*>(&u.y));
        float rx = di * fmaf(di, f0.x, a0);
        float ry = di * fmaf(di, f0.y, a1);
        float rz = di * fmaf(di, f1.x, a2);
        float rw = di * fmaf(di, f1.y, a3);
        uint2 o;
        *reinterpret_cast<__half2*>(&o.x) = __floats2half2_rn(rx, ry);
        *reinterpret_cast<__half2*>(&o.y) = __floats2half2_rn(rz, rw);
        *reinterpret_cast<uint2*>(&g_agg1h[(size_t)d * F + lane * PER]) = o;
    } else {
        uint32_t u = *reinterpret_cast<const uint32_t*>(hd);
        float2 f0 = __half22float2(*reinterpret_cast<const __half2*>(&u));
        float2 b = *reinterpret_cast<const float2*>(&b2[lane * PER]);
        float2 r;
        r.x = di * fmaf(di, f0.x, a0) + b.x;
        r.y = di * fmaf(di, f0.y, a1) + b.y;
        *reinterpret_cast<float2*>(&outp[(size_t)d * F + lane * PER]) = r;
    }
}

extern "C" void kernel_launch(void* const* d_in, const int* in_sizes, int n_in,
                              void* d_out, int out_size) {
    const float* x = (const float*)d_in[0];
    const void* ei = d_in[1];
    const float* W1 = (const float*)d_in[2];
    const float* b1 = (const float*)d_in[3];
    const float* W2 = (const float*)d_in[4];
    const float* b2 = (const float*)d_in[5];
    float* out = (float*)d_out;

    const int n = in_sizes[0] / F1;
    const int E = in_sizes[1] / 2;

    const int T = 256;

    // Fork: GEMM1 (depends only on x, W1) runs on a side stream concurrently
    // with the edge-preprocessing/CSR chain on the capture-origin stream.
    // Stream/event creation is not a captured op; handles are intentionally
    // not destroyed while capture may be active (few calls total, tiny leak).
    cudaStream_t s2;
    cudaStreamCreateWithFlags(&s2, cudaStreamNonBlocking);
    cudaEvent_t evFork, evJoin;
    cudaEventCreateWithFlags(&evFork, cudaEventDisableTiming);
    cudaEventCreateWithFlags(&evJoin, cudaEventDisableTiming);

    cudaEventRecord(evFork, 0);
    cudaStreamWaitEvent(s2, evFork, 0);
    // chain B: layer-1 GEMM on s2  (tf32 tensor cores, fp16 output)
    mma_gemm_kernel<128, false><<<(n + 127) / 128, 256, 0, s2>>>(x, W1, nullptr, n);
    cudaEventRecord(evJoin, s2);

    // chain A: edge dtype detect (+ zero degrees), normalize (+ degree count), CSR build
    detect_kernel<<<256, T>>>(ei, E, n);
    convert_kernel<<<(2 * E + T - 1) / T, T>>>(ei, E, n);
    int nb = (n + SCAN_T - 1) / SCAN_T;
    scan1_kernel<<<nb, SCAN_T>>>(n);
    scan2_kernel<<<nb, SCAN_T>>>(n, E);
    fill_kernel<<<(E + T - 1) / T, T>>>(E);

    // join: gather1 needs both g_h1h (chain B) and the CSR (chain A)
    cudaStreamWaitEvent(0, evJoin, 0);

    // g_agg1h = D^-1/2 (A+I) D^-1/2 h1   (CSR gather, fp16 out)
    gather_kernel<F1><<<(n * 32 + T - 1) / T, T>>>(nullptr, nullptr, n);

    // layer 2: g_h2h = relu(g_agg1h + b1) @ W2  (bias+relu fused into fp16 A-load)
    mma_gemm_kernel<64, true><<<(n + 127) / 128, 256>>>(nullptr, W2, b1, n);
    // out = D^-1/2 (A+I) D^-1/2 h2 + b2   (CSR gather, writes d_out fp32)
    gather_kernel<F2><<<(n * 32 + T - 1) / T, T>>>(b2, out, n);
}